// round 15
// baseline (speedup 1.0000x reference)
#include <cuda_runtime.h>
#include <cuda_bf16.h>

#define NB 16
#define LL 1024
#define DH 256
#define NEGINF (-1e30f)
#define FLT_LOW (-3.4e38f)

// ---------------- scratch (static device globals; no allocation) -------------
__device__ float g_sim[NB * LL * LL];                 // 67 MB scores
__device__ __nv_bfloat16 g_PWhi[NB * LL * DH];
__device__ __nv_bfloat16 g_PWlo[NB * LL * DH];
__device__ __nv_bfloat16 g_Hhi[NB * LL * DH];
__device__ __nv_bfloat16 g_Hlo[NB * LL * DH];
__device__ __nv_bfloat16 g_Phi[NB * LL * DH];
__device__ __nv_bfloat16 g_Plo[NB * LL * DH];
__device__ __nv_bfloat16 g_Wthi[DH * DH];             // W^T split: [e][d]
__device__ __nv_bfloat16 g_Wtlo[DH * DH];
__device__ float g_rowpm[8 * NB * LL];                // per-n-tile row max partials
__device__ float g_rowps[8 * NB * LL];                // per-n-tile row sumexp partials
__device__ float g_rowmax[NB * LL];
__device__ float g_rowinv[NB * LL];
__device__ float g_colpart[NB * 8 * LL];              // 8 p-chunks per batch
__device__ float g_pvec[NB * DH];

union BF8 { uint4 v; __nv_bfloat16 h[8]; };
union BF4 { uint2 v; __nv_bfloat16 h[4]; };
union BF2 { unsigned u; __nv_bfloat16 h[2]; };

__device__ __forceinline__ void mma_bf16(float d[4], const unsigned a[4], const unsigned b[2]) {
    asm volatile(
        "mma.sync.aligned.m16n8k16.row.col.f32.bf16.bf16.f32 "
        "{%0,%1,%2,%3}, {%4,%5,%6,%7}, {%8,%9}, {%0,%1,%2,%3};"
        : "+f"(d[0]), "+f"(d[1]), "+f"(d[2]), "+f"(d[3])
        : "r"(a[0]), "r"(a[1]), "r"(a[2]), "r"(a[3]), "r"(b[0]), "r"(b[1]));
}

__device__ __forceinline__ unsigned sm32(const void* p) {
    return (unsigned)__cvta_generic_to_shared(p);
}
__device__ __forceinline__ void ldsm4(unsigned* r, unsigned a) {
    asm volatile("ldmatrix.sync.aligned.m8n8.x4.shared.b16 {%0,%1,%2,%3}, [%4];"
                 : "=r"(r[0]), "=r"(r[1]), "=r"(r[2]), "=r"(r[3]) : "r"(a));
}
__device__ __forceinline__ void ldsm4t(unsigned* r, unsigned a) {
    asm volatile("ldmatrix.sync.aligned.m8n8.x4.trans.shared.b16 {%0,%1,%2,%3}, [%4];"
                 : "=r"(r[0]), "=r"(r[1]), "=r"(r[2]), "=r"(r[3]) : "r"(a));
}
__device__ __forceinline__ void cpa16(void* dst, const void* src) {
    asm volatile("cp.async.cg.shared.global [%0], [%1], 16;"
                 :: "r"(sm32(dst)), "l"(src));
}
#define CP_COMMIT asm volatile("cp.async.commit_group;")
#define CP_WAIT0  asm volatile("cp.async.wait_group 0;")
#define CP_WAIT1  asm volatile("cp.async.wait_group 1;")

__device__ __forceinline__ void split_bf16(float f, __nv_bfloat16& hi, __nv_bfloat16& lo) {
    hi = __float2bfloat16(f);
    lo = __float2bfloat16(f - __bfloat162float(hi));
}

// =============================================================================
// Kernel CVT (fused): H split, P split, W^T split
// =============================================================================
#define NHBLK ((NB * LL * DH) / (256 * 4))
__global__ void k_cvt_all(const float* __restrict__ H,
                          const float* __restrict__ P,
                          const float* __restrict__ W) {
    int blk = blockIdx.x;
    if (blk < NHBLK) {
        size_t i = ((size_t)blk * 256 + threadIdx.x) * 4;
        float4 v = *(const float4*)(H + i);
        BF4 hi, lo;
        split_bf16(v.x, hi.h[0], lo.h[0]);
        split_bf16(v.y, hi.h[1], lo.h[1]);
        split_bf16(v.z, hi.h[2], lo.h[2]);
        split_bf16(v.w, hi.h[3], lo.h[3]);
        *(uint2*)&g_Hhi[i] = hi.v;
        *(uint2*)&g_Hlo[i] = lo.v;
    } else if (blk < 2 * NHBLK) {
        size_t i = ((size_t)(blk - NHBLK) * 256 + threadIdx.x) * 4;
        float4 v = *(const float4*)(P + i);
        BF4 hi, lo;
        split_bf16(v.x, hi.h[0], lo.h[0]);
        split_bf16(v.y, hi.h[1], lo.h[1]);
        split_bf16(v.z, hi.h[2], lo.h[2]);
        split_bf16(v.w, hi.h[3], lo.h[3]);
        *(uint2*)&g_Phi[i] = hi.v;
        *(uint2*)&g_Plo[i] = lo.v;
    } else {
        int idx = (blk - 2 * NHBLK) * 256 + threadIdx.x;   // 65536 total
        int d = idx >> 8, e = idx & 255;
        float v = W[idx];
        __nv_bfloat16 hi, lo;
        split_bf16(v, hi, lo);
        g_Wthi[e * DH + d] = hi;
        g_Wtlo[e * DH + d] = lo;
    }
}

// =============================================================================
// Shared GEMM body (NT, split-bf16 3-product, cp.async double-buffer, ldmatrix)
// Prefetch committed BEFORE waiting on current stage (wait_group 1).
// Trailing __syncthreads guards buffer reuse.
// =============================================================================
#define STG (4 * 128 * 40)        // halfwords per stage
#define ARR (128 * 40)

template<int KDIM>
__device__ __forceinline__ void gemm_nt_body(
    __nv_bfloat16* sm,
    const __nv_bfloat16* __restrict__ Aghi, const __nv_bfloat16* __restrict__ Aglo,
    const __nv_bfloat16* __restrict__ Bghi, const __nv_bfloat16* __restrict__ Bglo,
    size_t abase, size_t bbase, float acc[4][4][4],
    int wm, int wn, int lane)
{
    const int tid = threadIdx.x;
    const int lrow = tid >> 1, lseg = (tid & 1) * 16;
    const int arow = wm + (lane & 15), acol = (lane >> 4) * 8;
    const int bro  = (lane & 7) + ((lane >> 4) & 1) * 8;
    const int bco  = ((lane >> 3) & 1) * 8;
    const int soff = lrow * 40 + lseg;

    {
        __nv_bfloat16* st = sm;
        cpa16(st + soff,              Aghi + abase);
        cpa16(st + soff + 8,          Aghi + abase + 8);
        cpa16(st + ARR + soff,        Aglo + abase);
        cpa16(st + ARR + soff + 8,    Aglo + abase + 8);
        cpa16(st + 2*ARR + soff,      Bghi + bbase);
        cpa16(st + 2*ARR + soff + 8,  Bghi + bbase + 8);
        cpa16(st + 3*ARR + soff,      Bglo + bbase);
        cpa16(st + 3*ARR + soff + 8,  Bglo + bbase + 8);
        CP_COMMIT;
    }
    int s = 0;
    for (int k0 = 0; k0 < KDIM; k0 += 32, s ^= 1) {
        if (k0 + 32 < KDIM) {
            // issue next-stage prefetch BEFORE waiting on current stage
            __nv_bfloat16* st = sm + (s ^ 1) * STG;
            size_t ao = abase + k0 + 32, bo = bbase + k0 + 32;
            cpa16(st + soff,              Aghi + ao);
            cpa16(st + soff + 8,          Aghi + ao + 8);
            cpa16(st + ARR + soff,        Aglo + ao);
            cpa16(st + ARR + soff + 8,    Aglo + ao + 8);
            cpa16(st + 2*ARR + soff,      Bghi + bo);
            cpa16(st + 2*ARR + soff + 8,  Bghi + bo + 8);
            cpa16(st + 3*ARR + soff,      Bglo + bo);
            cpa16(st + 3*ARR + soff + 8,  Bglo + bo + 8);
            CP_COMMIT;
            CP_WAIT1;                     // drain only the older group
        } else {
            CP_WAIT0;
        }
        __syncthreads();
        const __nv_bfloat16* Ah = sm + s * STG;
        const __nv_bfloat16* Al = Ah + ARR;
        const __nv_bfloat16* Bh = Ah + 2 * ARR;
        const __nv_bfloat16* Bl = Ah + 3 * ARR;
#pragma unroll
        for (int ks = 0; ks < 32; ks += 16) {
            unsigned afh[4][4], afl[4][4];
#pragma unroll
            for (int mt = 0; mt < 4; mt++) {
                ldsm4(afh[mt], sm32(Ah + (arow + mt * 16) * 40 + ks + acol));
                ldsm4(afl[mt], sm32(Al + (arow + mt * 16) * 40 + ks + acol));
            }
#pragma unroll
            for (int p = 0; p < 2; p++) {
                unsigned bh4[4], bl4[4];
                ldsm4(bh4, sm32(Bh + (wn + p * 16 + bro) * 40 + ks + bco));
                ldsm4(bl4, sm32(Bl + (wn + p * 16 + bro) * 40 + ks + bco));
#pragma unroll
                for (int mt = 0; mt < 4; mt++)
#pragma unroll
                    for (int q = 0; q < 2; q++)
                        mma_bf16(acc[mt][p * 2 + q], afh[mt], &bh4[2 * q]);
#pragma unroll
                for (int mt = 0; mt < 4; mt++)
#pragma unroll
                    for (int q = 0; q < 2; q++)
                        mma_bf16(acc[mt][p * 2 + q], afh[mt], &bl4[2 * q]);
#pragma unroll
                for (int mt = 0; mt < 4; mt++)
#pragma unroll
                    for (int q = 0; q < 2; q++)
                        mma_bf16(acc[mt][p * 2 + q], afl[mt], &bh4[2 * q]);
            }
        }
        __syncthreads();    // guards next-iteration prefetch overwriting this buffer
    }
}

// =============================================================================
// Kernel A: PW = P @ Wt^T
// =============================================================================
__global__ __launch_bounds__(256, 2) void k_pw_mma() {
    extern __shared__ __align__(16) __nv_bfloat16 sm[];
    const int bm = blockIdx.y * 128, bn = blockIdx.x * 128;
    const int tid = threadIdx.x, warp = tid >> 5, lane = tid & 31;
    const int wm = (warp >> 2) * 64, wn = (warp & 3) * 32;
    const int gid = lane >> 2, tig = lane & 3;
    const int lrow = tid >> 1, lseg = (tid & 1) * 16;

    float acc[4][4][4];
#pragma unroll
    for (int mt = 0; mt < 4; mt++)
#pragma unroll
        for (int nt = 0; nt < 4; nt++)
#pragma unroll
            for (int e = 0; e < 4; e++) acc[mt][nt][e] = 0.0f;

    gemm_nt_body<DH>(sm, g_Phi, g_Plo, g_Wthi, g_Wtlo,
                     (size_t)(bm + lrow) * DH + lseg,
                     (size_t)(bn + lrow) * DH + lseg,
                     acc, wm, wn, lane);

#pragma unroll
    for (int mt = 0; mt < 4; mt++) {
        int r0 = bm + wm + mt * 16 + gid, r1 = r0 + 8;
#pragma unroll
        for (int nt = 0; nt < 4; nt++) {
            int c = bn + wn + nt * 8 + tig * 2;
            float* d = acc[mt][nt];
            BF2 h0, l0, h1, l1;
            split_bf16(d[0], h0.h[0], l0.h[0]);
            split_bf16(d[1], h0.h[1], l0.h[1]);
            split_bf16(d[2], h1.h[0], l1.h[0]);
            split_bf16(d[3], h1.h[1], l1.h[1]);
            *(unsigned*)&g_PWhi[(size_t)r0 * DH + c] = h0.u;
            *(unsigned*)&g_PWlo[(size_t)r0 * DH + c] = l0.u;
            *(unsigned*)&g_PWhi[(size_t)r1 * DH + c] = h1.u;
            *(unsigned*)&g_PWlo[(size_t)r1 * DH + c] = l1.u;
        }
    }
}

// =============================================================================
// Kernel B: sim[b] = PW[b] @ H[b]^T + bias + mask, WITH fused stats partials
// =============================================================================
__global__ __launch_bounds__(256, 2) void k_sim(const int* __restrict__ pmask,
                                                const int* __restrict__ hmask,
                                                const float* __restrict__ bias) {
    extern __shared__ __align__(16) __nv_bfloat16 sm[];
    const int b = blockIdx.z;
    const int bm = blockIdx.y * 128, bn = blockIdx.x * 128;
    const int tid = threadIdx.x, warp = tid >> 5, lane = tid & 31;
    const int wm = (warp >> 2) * 64, wn = (warp & 3) * 32;
    const int gid = lane >> 2, tig = lane & 3;
    const int lrow = tid >> 1, lseg = (tid & 1) * 16;

    float acc[4][4][4];
#pragma unroll
    for (int mt = 0; mt < 4; mt++)
#pragma unroll
        for (int nt = 0; nt < 4; nt++)
#pragma unroll
            for (int e = 0; e < 4; e++) acc[mt][nt][e] = 0.0f;

    gemm_nt_body<DH>(sm, g_PWhi, g_PWlo, g_Hhi, g_Hlo,
                     ((size_t)b * LL + bm + lrow) * DH + lseg,
                     ((size_t)b * LL + bn + lrow) * DH + lseg,
                     acc, wm, wn, lane);

    const float bb = bias[0];
#pragma unroll
    for (int mt = 0; mt < 4; mt++) {
        int r0 = bm + wm + mt * 16 + gid, r1 = r0 + 8;
        float pm0 = (float)pmask[b * LL + r0];
        float pm1 = (float)pmask[b * LL + r1];
#pragma unroll
        for (int nt = 0; nt < 4; nt++) {
            int c = bn + wn + nt * 8 + tig * 2;
            float hm0 = (float)hmask[b * LL + c];
            float hm1 = (float)hmask[b * LL + c + 1];
            float* d = acc[mt][nt];
            d[0] += bb + (1.0f - pm0 * hm0) * NEGINF;
            d[1] += bb + (1.0f - pm0 * hm1) * NEGINF;
            d[2] += bb + (1.0f - pm1 * hm0) * NEGINF;
            d[3] += bb + (1.0f - pm1 * hm1) * NEGINF;
            *(float2*)&g_sim[((size_t)b * LL + r0) * LL + c] = make_float2(d[0], d[1]);
            *(float2*)&g_sim[((size_t)b * LL + r1) * LL + c] = make_float2(d[2], d[3]);
        }
    }

    // ---- fused stats partials (reuse smem as float scratch) ----
    float* S = (float*)sm;
    float* rowmS = S;            // [4][128]
    float* rowsS = S + 512;      // [4][128]
    float* colmS = S + 1024;     // [2][128]
    const int wng = warp & 3, wrow = warp >> 2;
    __syncthreads();

#pragma unroll
    for (int mt = 0; mt < 4; mt++) {
        float m0 = FLT_LOW, m1 = FLT_LOW;
#pragma unroll
        for (int nt = 0; nt < 4; nt++) {
            m0 = fmaxf(m0, fmaxf(acc[mt][nt][0], acc[mt][nt][1]));
            m1 = fmaxf(m1, fmaxf(acc[mt][nt][2], acc[mt][nt][3]));
        }
        m0 = fmaxf(m0, __shfl_xor_sync(0xffffffffu, m0, 1));
        m0 = fmaxf(m0, __shfl_xor_sync(0xffffffffu, m0, 2));
        m1 = fmaxf(m1, __shfl_xor_sync(0xffffffffu, m1, 1));
        m1 = fmaxf(m1, __shfl_xor_sync(0xffffffffu, m1, 2));
        if (tig == 0) {
            rowmS[wng * 128 + wm + mt * 16 + gid]     = m0;
            rowmS[wng * 128 + wm + mt * 16 + gid + 8] = m1;
        }
    }
#pragma unroll
    for (int nt = 0; nt < 4; nt++) {
        float c0 = FLT_LOW, c1 = FLT_LOW;
#pragma unroll
        for (int mt = 0; mt < 4; mt++) {
            c0 = fmaxf(c0, fmaxf(acc[mt][nt][0], acc[mt][nt][2]));
            c1 = fmaxf(c1, fmaxf(acc[mt][nt][1], acc[mt][nt][3]));
        }
        c0 = fmaxf(c0, __shfl_xor_sync(0xffffffffu, c0, 4));
        c0 = fmaxf(c0, __shfl_xor_sync(0xffffffffu, c0, 8));
        c0 = fmaxf(c0, __shfl_xor_sync(0xffffffffu, c0, 16));
        c1 = fmaxf(c1, __shfl_xor_sync(0xffffffffu, c1, 4));
        c1 = fmaxf(c1, __shfl_xor_sync(0xffffffffu, c1, 8));
        c1 = fmaxf(c1, __shfl_xor_sync(0xffffffffu, c1, 16));
        if (gid == 0) {
            colmS[wrow * 128 + wn + nt * 8 + tig * 2]     = c0;
            colmS[wrow * 128 + wn + nt * 8 + tig * 2 + 1] = c1;
        }
    }
    __syncthreads();

#pragma unroll
    for (int mt = 0; mt < 4; mt++) {
        int lr0 = wm + mt * 16 + gid, lr1 = lr0 + 8;
        float m0 = fmaxf(fmaxf(rowmS[lr0], rowmS[128 + lr0]),
                         fmaxf(rowmS[256 + lr0], rowmS[384 + lr0]));
        float m1 = fmaxf(fmaxf(rowmS[lr1], rowmS[128 + lr1]),
                         fmaxf(rowmS[256 + lr1], rowmS[384 + lr1]));
        float s0 = 0.0f, s1 = 0.0f;
#pragma unroll
        for (int nt = 0; nt < 4; nt++) {
            s0 += __expf(acc[mt][nt][0] - m0) + __expf(acc[mt][nt][1] - m0);
            s1 += __expf(acc[mt][nt][2] - m1) + __expf(acc[mt][nt][3] - m1);
        }
        s0 += __shfl_xor_sync(0xffffffffu, s0, 1);
        s0 += __shfl_xor_sync(0xffffffffu, s0, 2);
        s1 += __shfl_xor_sync(0xffffffffu, s1, 1);
        s1 += __shfl_xor_sync(0xffffffffu, s1, 2);
        if (tig == 0) {
            rowsS[wng * 128 + lr0] = s0;
            rowsS[wng * 128 + lr1] = s1;
        }
    }
    __syncthreads();

    if (tid < 128) {
        float m = fmaxf(fmaxf(rowmS[tid], rowmS[128 + tid]),
                        fmaxf(rowmS[256 + tid], rowmS[384 + tid]));
        float s = rowsS[tid] + rowsS[128 + tid] + rowsS[256 + tid] + rowsS[384 + tid];
        size_t ro = (size_t)blockIdx.x * (NB * LL) + (size_t)b * LL + bm + tid;
        g_rowpm[ro] = m;
        g_rowps[ro] = s;
        float cm = fmaxf(colmS[tid], colmS[128 + tid]);
        g_colpart[((size_t)b * 8 + blockIdx.y) * LL + bn + tid] = cm;
    }
}

// =============================================================================
// Kernel C2: combine 8 row partials -> rowmax / rowinv
// =============================================================================
__global__ void k_finstats() {
    int row = blockIdx.x * 256 + threadIdx.x;     // < NB*LL
    float mj[8];
    float m = FLT_LOW;
#pragma unroll
    for (int j = 0; j < 8; j++) {
        mj[j] = g_rowpm[j * (NB * LL) + row];
        m = fmaxf(m, mj[j]);
    }
    float s = 0.0f;
#pragma unroll
    for (int j = 0; j < 8; j++)
        s += g_rowps[j * (NB * LL) + row] * __expf(mj[j] - m);
    g_rowmax[row] = m;
    g_rowinv[row] = 1.0f / s;
}

// =============================================================================
// Kernel D: aligned_hyp[b] = softmax(sim[b]) @ H[b]  (cp.async, ldmatrix.trans)
// Prefetch-before-wait pipeline WITH trailing barrier (race fix).
// =============================================================================
#define AV_AH 0
#define AV_AL 5120
#define AV_B(s) (10240 + (s) * 8704)
#define AV_SRAW_H 27648
#define AV_SMEM_BYTES (55296 + 2 * 128 * 36 * 4)

__global__ __launch_bounds__(256, 2) void k_av(float* __restrict__ out) {
    extern __shared__ __align__(16) __nv_bfloat16 sm[];
    float* Sraw = (float*)(sm + AV_SRAW_H);
    const int b = blockIdx.z;
    const int bm = blockIdx.y * 128, bn = blockIdx.x * 128;   // bn over DH
    const int tid = threadIdx.x, warp = tid >> 5, lane = tid & 31;
    const int wm = (warp >> 2) * 64, wn = (warp & 3) * 32;
    const int gid = lane >> 2, tig = lane & 3;
    const int lrow = tid >> 1, lseg = (tid & 1) * 16;
    const int arow = wm + (lane & 15), acol = (lane >> 4) * 8;
    const int tkr = (lane & 7) + ((lane >> 3) & 1) * 8;
    const int tdc = ((lane >> 4) & 1) * 8;
    const int qr = tid >> 3, dc = (tid & 7) * 16;

    const float rm = g_rowmax[b * LL + bm + lrow];
    const float ri = g_rowinv[b * LL + bm + lrow];
    const float* sp = &g_sim[((size_t)b * LL + bm + lrow) * LL + lseg];

    float acc[4][4][4];
#pragma unroll
    for (int mt = 0; mt < 4; mt++)
#pragma unroll
        for (int nt = 0; nt < 4; nt++)
#pragma unroll
            for (int e = 0; e < 4; e++) acc[mt][nt][e] = 0.0f;

    {
        float* sr = Sraw + lrow * 36 + lseg;
        cpa16(sr,      sp);
        cpa16(sr + 4,  sp + 4);
        cpa16(sr + 8,  sp + 8);
        cpa16(sr + 12, sp + 12);
        size_t hb = ((size_t)b * LL + qr) * DH + bn + dc;
        __nv_bfloat16* bh = sm + AV_B(0) + qr * 136 + dc;
        cpa16(bh,            &g_Hhi[hb]);
        cpa16(bh + 8,        &g_Hhi[hb + 8]);
        cpa16(bh + 4352,     &g_Hlo[hb]);
        cpa16(bh + 4352 + 8, &g_Hlo[hb + 8]);
        CP_COMMIT;
    }
    int s = 0;
    for (int k0 = 0; k0 < LL; k0 += 32, s ^= 1) {
        if (k0 + 32 < LL) {
            float* sr = Sraw + (s ^ 1) * 128 * 36 + lrow * 36 + lseg;
            const float* spn = sp + k0 + 32;
            cpa16(sr,      spn);
            cpa16(sr + 4,  spn + 4);
            cpa16(sr + 8,  spn + 8);
            cpa16(sr + 12, spn + 12);
            size_t hb = ((size_t)b * LL + k0 + 32 + qr) * DH + bn + dc;
            __nv_bfloat16* bh = sm + AV_B(s ^ 1) + qr * 136 + dc;
            cpa16(bh,            &g_Hhi[hb]);
            cpa16(bh + 8,        &g_Hhi[hb + 8]);
            cpa16(bh + 4352,     &g_Hlo[hb]);
            cpa16(bh + 4352 + 8, &g_Hlo[hb + 8]);
            CP_COMMIT;
            CP_WAIT1;
        } else {
            CP_WAIT0;
        }
        __syncthreads();
        {
            const float* sr = Sraw + s * 128 * 36 + lrow * 36 + lseg;
            BF8 phi0, phi1, plo0, plo1;
#pragma unroll
            for (int i = 0; i < 8; i++) {
                float p0 = __expf(sr[i] - rm) * ri;
                float p1 = __expf(sr[8 + i] - rm) * ri;
                split_bf16(p0, phi0.h[i], plo0.h[i]);
                split_bf16(p1, phi1.h[i], plo1.h[i]);
            }
            *(uint4*)(sm + AV_AH + lrow * 40 + lseg)     = phi0.v;
            *(uint4*)(sm + AV_AH + lrow * 40 + lseg + 8) = phi1.v;
            *(uint4*)(sm + AV_AL + lrow * 40 + lseg)     = plo0.v;
            *(uint4*)(sm + AV_AL + lrow * 40 + lseg + 8) = plo1.v;
        }
        __syncthreads();
        const __nv_bfloat16* Bhs = sm + AV_B(s);
        const __nv_bfloat16* Bls = Bhs + 4352;
#pragma unroll
        for (int ks = 0; ks < 32; ks += 16) {
            unsigned afh[4][4], afl[4][4];
#pragma unroll
            for (int mt = 0; mt < 4; mt++) {
                ldsm4(afh[mt], sm32(sm + AV_AH + (arow + mt * 16) * 40 + ks + acol));
                ldsm4(afl[mt], sm32(sm + AV_AL + (arow + mt * 16) * 40 + ks + acol));
            }
#pragma unroll
            for (int p = 0; p < 2; p++) {
                unsigned bh4[4], bl4[4];
                ldsm4t(bh4, sm32(Bhs + (ks + tkr) * 136 + wn + p * 16 + tdc));
                ldsm4t(bl4, sm32(Bls + (ks + tkr) * 136 + wn + p * 16 + tdc));
#pragma unroll
                for (int mt = 0; mt < 4; mt++)
#pragma unroll
                    for (int q = 0; q < 2; q++)
                        mma_bf16(acc[mt][p * 2 + q], afh[mt], &bh4[2 * q]);
#pragma unroll
                for (int mt = 0; mt < 4; mt++)
#pragma unroll
                    for (int q = 0; q < 2; q++)
                        mma_bf16(acc[mt][p * 2 + q], afh[mt], &bl4[2 * q]);
#pragma unroll
                for (int mt = 0; mt < 4; mt++)
#pragma unroll
                    for (int q = 0; q < 2; q++)
                        mma_bf16(acc[mt][p * 2 + q], afl[mt], &bh4[2 * q]);
            }
        }
        __syncthreads();    // RACE FIX: next prefetch overwrites Bhs(s)/Sraw(s)
    }
#pragma unroll
    for (int mt = 0; mt < 4; mt++) {
        int r0 = bm + wm + mt * 16 + gid, r1 = r0 + 8;
#pragma unroll
        for (int nt = 0; nt < 4; nt++) {
            int c = bn + wn + nt * 8 + tig * 2;
            float* d = acc[mt][nt];
            *(float2*)&out[((size_t)b * LL + r0) * DH + c] = make_float2(d[0], d[1]);
            *(float2*)&out[((size_t)b * LL + r1) * DH + c] = make_float2(d[2], d[3]);
        }
    }
}

// =============================================================================
// Kernel E: per batch — softmax(colmax over 8 partials) @ P -> g_pvec
// =============================================================================
__global__ __launch_bounds__(256) void k_premise(const float* __restrict__ P) {
    const int b = blockIdx.x;
    const int t = threadIdx.x;
    __shared__ float prob[LL];
    __shared__ float red[8];
    float loc[4];
#pragma unroll
    for (int c = 0; c < 4; c++) {
        int q = c * 256 + t;
        float m = FLT_LOW;
#pragma unroll
        for (int j = 0; j < 8; j++)
            m = fmaxf(m, g_colpart[((size_t)b * 8 + j) * LL + q]);
        loc[c] = m;
    }
    float mx = fmaxf(fmaxf(loc[0], loc[1]), fmaxf(loc[2], loc[3]));
#pragma unroll
    for (int o = 16; o > 0; o >>= 1) mx = fmaxf(mx, __shfl_xor_sync(0xffffffffu, mx, o));
    const int w = t >> 5, lane = t & 31;
    if (lane == 0) red[w] = mx;
    __syncthreads();
    mx = red[0];
#pragma unroll
    for (int j = 1; j < 8; j++) mx = fmaxf(mx, red[j]);

    float se = 0.0f;
#pragma unroll
    for (int c = 0; c < 4; c++) {
        float e = __expf(loc[c] - mx);
        prob[c * 256 + t] = e;
        se += e;
    }
#pragma unroll
    for (int o = 16; o > 0; o >>= 1) se += __shfl_xor_sync(0xffffffffu, se, o);
    __syncthreads();
    if (lane == 0) red[w] = se;
    __syncthreads();
    float tot = 0.0f;
#pragma unroll
    for (int j = 0; j < 8; j++) tot += red[j];
    const float inv = 1.0f / tot;

    const float* Pb = P + (size_t)b * LL * DH + t;
    float acc = 0.0f;
#pragma unroll 8
    for (int q = 0; q < LL; q++)
        acc = fmaf(prob[q], Pb[(size_t)q * DH], acc);
    g_pvec[b * DH + t] = acc * inv;
}

// =============================================================================
// Kernel F: broadcast g_pvec -> out[0 : NB*LL*DH)
// =============================================================================
__global__ void k_bcast(float* __restrict__ out) {
    int idx = (blockIdx.x * 256 + threadIdx.x) * 4;
    int b = idx >> 18;
    int d = idx & (DH - 1);
    float4 v = *(const float4*)&g_pvec[b * DH + d];
    *(float4*)&out[idx] = v;
}

// =============================================================================
extern "C" void kernel_launch(void* const* d_in, const int* in_sizes, int n_in,
                              void* d_out, int out_size) {
    const float* P    = (const float*)d_in[0];
    const float* Hh   = (const float*)d_in[1];
    const int*   pm   = (const int*)d_in[2];
    const int*   hm   = (const int*)d_in[3];
    const float* W    = (const float*)d_in[4];
    const float* bias = (const float*)d_in[5];
    float* out = (float*)d_out;

    const int gemm_smem = 2 * STG * 2;            // 81920 bytes
    cudaFuncSetAttribute(k_pw_mma, cudaFuncAttributeMaxDynamicSharedMemorySize, gemm_smem);
    cudaFuncSetAttribute(k_sim,    cudaFuncAttributeMaxDynamicSharedMemorySize, gemm_smem);
    cudaFuncSetAttribute(k_av,     cudaFuncAttributeMaxDynamicSharedMemorySize, AV_SMEM_BYTES);

    k_cvt_all  <<<2 * NHBLK + DH * DH / 256, 256>>>(Hh, P, W);
    k_pw_mma   <<<dim3(DH / 128, (NB * LL) / 128), 256, gemm_smem>>>();
    k_sim      <<<dim3(LL / 128, LL / 128, NB), 256, gemm_smem>>>(pm, hm, bias);
    k_finstats <<<(NB * LL) / 256, 256>>>();
    k_av       <<<dim3(DH / 128, LL / 128, NB), 256, AV_SMEM_BYTES>>>(out + (size_t)NB * LL * DH);
    k_premise  <<<NB, 256>>>(P);
    k_bcast    <<<(NB * LL * DH) / (256 * 4), 256>>>(out);
}

// round 17
// speedup vs baseline: 1.0967x; 1.0967x over previous
#include <cuda_runtime.h>
#include <cuda_bf16.h>
#include <cuda_fp16.h>

#define NB 16
#define LL 1024
#define DH 256
#define NEGINF (-1e30f)
#define FLT_LOW (-3.4e38f)

// ---------------- scratch (static device globals; no allocation) -------------
__device__ float g_sim[NB * LL * LL];                 // 67 MB scores
__device__ __nv_bfloat16 g_PWhi[NB * LL * DH];
__device__ __nv_bfloat16 g_PWlo[NB * LL * DH];
__device__ __nv_bfloat16 g_Hhi[NB * LL * DH];
__device__ __nv_bfloat16 g_Hlo[NB * LL * DH];
__device__ __half g_Hfh[NB * LL * DH];                // H fp16 split (k_av path)
__device__ __half g_Hfl[NB * LL * DH];
__device__ __nv_bfloat16 g_Phi[NB * LL * DH];
__device__ __nv_bfloat16 g_Plo[NB * LL * DH];
__device__ __nv_bfloat16 g_Wthi[DH * DH];             // W^T split: [e][d]
__device__ __nv_bfloat16 g_Wtlo[DH * DH];
__device__ float g_rowpm[8 * NB * LL];                // per-n-tile row max partials
__device__ float g_rowps[8 * NB * LL];                // per-n-tile row sumexp partials
__device__ float g_rowmax[NB * LL];
__device__ float g_rowinv[NB * LL];
__device__ float g_colpart[NB * 8 * LL];              // 8 p-chunks per batch
__device__ float g_pvec[NB * DH];

union BF8 { uint4 v; __nv_bfloat16 h[8]; };
union BF4 { uint2 v; __nv_bfloat16 h[4]; };
union BF2 { unsigned u; __nv_bfloat16 h[2]; };
union HF8 { uint4 v; __half h[8]; };
union HF4 { uint2 v; __half h[4]; };

__device__ __forceinline__ void mma_bf16(float d[4], const unsigned a[4], const unsigned b[2]) {
    asm volatile(
        "mma.sync.aligned.m16n8k16.row.col.f32.bf16.bf16.f32 "
        "{%0,%1,%2,%3}, {%4,%5,%6,%7}, {%8,%9}, {%0,%1,%2,%3};"
        : "+f"(d[0]), "+f"(d[1]), "+f"(d[2]), "+f"(d[3])
        : "r"(a[0]), "r"(a[1]), "r"(a[2]), "r"(a[3]), "r"(b[0]), "r"(b[1]));
}
__device__ __forceinline__ void mma_f16(float d[4], const unsigned a[4], const unsigned b[2]) {
    asm volatile(
        "mma.sync.aligned.m16n8k16.row.col.f32.f16.f16.f32 "
        "{%0,%1,%2,%3}, {%4,%5,%6,%7}, {%8,%9}, {%0,%1,%2,%3};"
        : "+f"(d[0]), "+f"(d[1]), "+f"(d[2]), "+f"(d[3])
        : "r"(a[0]), "r"(a[1]), "r"(a[2]), "r"(a[3]), "r"(b[0]), "r"(b[1]));
}

__device__ __forceinline__ unsigned sm32(const void* p) {
    return (unsigned)__cvta_generic_to_shared(p);
}
__device__ __forceinline__ void ldsm4(unsigned* r, unsigned a) {
    asm volatile("ldmatrix.sync.aligned.m8n8.x4.shared.b16 {%0,%1,%2,%3}, [%4];"
                 : "=r"(r[0]), "=r"(r[1]), "=r"(r[2]), "=r"(r[3]) : "r"(a));
}
__device__ __forceinline__ void ldsm4t(unsigned* r, unsigned a) {
    asm volatile("ldmatrix.sync.aligned.m8n8.x4.trans.shared.b16 {%0,%1,%2,%3}, [%4];"
                 : "=r"(r[0]), "=r"(r[1]), "=r"(r[2]), "=r"(r[3]) : "r"(a));
}
__device__ __forceinline__ void cpa16(void* dst, const void* src) {
    asm volatile("cp.async.cg.shared.global [%0], [%1], 16;"
                 :: "r"(sm32(dst)), "l"(src));
}
#define CP_COMMIT asm volatile("cp.async.commit_group;")
#define CP_WAIT0  asm volatile("cp.async.wait_group 0;")
#define CP_WAIT1  asm volatile("cp.async.wait_group 1;")

__device__ __forceinline__ void split_bf16(float f, __nv_bfloat16& hi, __nv_bfloat16& lo) {
    hi = __float2bfloat16(f);
    lo = __float2bfloat16(f - __bfloat162float(hi));
}
__device__ __forceinline__ void split_f16(float f, __half& hi, __half& lo) {
    hi = __float2half_rn(f);
    lo = __float2half_rn(f - __half2float(hi));
}

// =============================================================================
// Kernel CVT (fused): H split (bf16 + fp16), P split, W^T split
// =============================================================================
#define NHBLK ((NB * LL * DH) / (256 * 4))
__global__ void k_cvt_all(const float* __restrict__ H,
                          const float* __restrict__ P,
                          const float* __restrict__ W) {
    int blk = blockIdx.x;
    if (blk < NHBLK) {
        size_t i = ((size_t)blk * 256 + threadIdx.x) * 4;
        float4 v = *(const float4*)(H + i);
        BF4 hi, lo;
        split_bf16(v.x, hi.h[0], lo.h[0]);
        split_bf16(v.y, hi.h[1], lo.h[1]);
        split_bf16(v.z, hi.h[2], lo.h[2]);
        split_bf16(v.w, hi.h[3], lo.h[3]);
        *(uint2*)&g_Hhi[i] = hi.v;
        *(uint2*)&g_Hlo[i] = lo.v;
        HF4 fh, fl;
        split_f16(v.x, fh.h[0], fl.h[0]);
        split_f16(v.y, fh.h[1], fl.h[1]);
        split_f16(v.z, fh.h[2], fl.h[2]);
        split_f16(v.w, fh.h[3], fl.h[3]);
        *(uint2*)&g_Hfh[i] = fh.v;
        *(uint2*)&g_Hfl[i] = fl.v;
    } else if (blk < 2 * NHBLK) {
        size_t i = ((size_t)(blk - NHBLK) * 256 + threadIdx.x) * 4;
        float4 v = *(const float4*)(P + i);
        BF4 hi, lo;
        split_bf16(v.x, hi.h[0], lo.h[0]);
        split_bf16(v.y, hi.h[1], lo.h[1]);
        split_bf16(v.z, hi.h[2], lo.h[2]);
        split_bf16(v.w, hi.h[3], lo.h[3]);
        *(uint2*)&g_Phi[i] = hi.v;
        *(uint2*)&g_Plo[i] = lo.v;
    } else {
        int idx = (blk - 2 * NHBLK) * 256 + threadIdx.x;   // 65536 total
        int d = idx >> 8, e = idx & 255;
        float v = W[idx];
        __nv_bfloat16 hi, lo;
        split_bf16(v, hi, lo);
        g_Wthi[e * DH + d] = hi;
        g_Wtlo[e * DH + d] = lo;
    }
}

// =============================================================================
// Shared GEMM body (NT, split-bf16 3-product, cp.async double-buffer, ldmatrix)
// =============================================================================
#define STG (4 * 128 * 40)        // halfwords per stage
#define ARR (128 * 40)

template<int KDIM>
__device__ __forceinline__ void gemm_nt_body(
    __nv_bfloat16* sm,
    const __nv_bfloat16* __restrict__ Aghi, const __nv_bfloat16* __restrict__ Aglo,
    const __nv_bfloat16* __restrict__ Bghi, const __nv_bfloat16* __restrict__ Bglo,
    size_t abase, size_t bbase, float acc[4][4][4],
    int wm, int wn, int lane)
{
    const int tid = threadIdx.x;
    const int lrow = tid >> 1, lseg = (tid & 1) * 16;
    const int arow = wm + (lane & 15), acol = (lane >> 4) * 8;
    const int bro  = (lane & 7) + ((lane >> 4) & 1) * 8;
    const int bco  = ((lane >> 3) & 1) * 8;
    const int soff = lrow * 40 + lseg;

    {
        __nv_bfloat16* st = sm;
        cpa16(st + soff,              Aghi + abase);
        cpa16(st + soff + 8,          Aghi + abase + 8);
        cpa16(st + ARR + soff,        Aglo + abase);
        cpa16(st + ARR + soff + 8,    Aglo + abase + 8);
        cpa16(st + 2*ARR + soff,      Bghi + bbase);
        cpa16(st + 2*ARR + soff + 8,  Bghi + bbase + 8);
        cpa16(st + 3*ARR + soff,      Bglo + bbase);
        cpa16(st + 3*ARR + soff + 8,  Bglo + bbase + 8);
        CP_COMMIT;
    }
    int s = 0;
    for (int k0 = 0; k0 < KDIM; k0 += 32, s ^= 1) {
        if (k0 + 32 < KDIM) {
            __nv_bfloat16* st = sm + (s ^ 1) * STG;
            size_t ao = abase + k0 + 32, bo = bbase + k0 + 32;
            cpa16(st + soff,              Aghi + ao);
            cpa16(st + soff + 8,          Aghi + ao + 8);
            cpa16(st + ARR + soff,        Aglo + ao);
            cpa16(st + ARR + soff + 8,    Aglo + ao + 8);
            cpa16(st + 2*ARR + soff,      Bghi + bo);
            cpa16(st + 2*ARR + soff + 8,  Bghi + bo + 8);
            cpa16(st + 3*ARR + soff,      Bglo + bo);
            cpa16(st + 3*ARR + soff + 8,  Bglo + bo + 8);
            CP_COMMIT;
            CP_WAIT1;
        } else {
            CP_WAIT0;
        }
        __syncthreads();
        const __nv_bfloat16* Ah = sm + s * STG;
        const __nv_bfloat16* Al = Ah + ARR;
        const __nv_bfloat16* Bh = Ah + 2 * ARR;
        const __nv_bfloat16* Bl = Ah + 3 * ARR;
#pragma unroll
        for (int ks = 0; ks < 32; ks += 16) {
            unsigned afh[4][4], afl[4][4];
#pragma unroll
            for (int mt = 0; mt < 4; mt++) {
                ldsm4(afh[mt], sm32(Ah + (arow + mt * 16) * 40 + ks + acol));
                ldsm4(afl[mt], sm32(Al + (arow + mt * 16) * 40 + ks + acol));
            }
#pragma unroll
            for (int p = 0; p < 2; p++) {
                unsigned bh4[4], bl4[4];
                ldsm4(bh4, sm32(Bh + (wn + p * 16 + bro) * 40 + ks + bco));
                ldsm4(bl4, sm32(Bl + (wn + p * 16 + bro) * 40 + ks + bco));
#pragma unroll
                for (int mt = 0; mt < 4; mt++)
#pragma unroll
                    for (int q = 0; q < 2; q++)
                        mma_bf16(acc[mt][p * 2 + q], afh[mt], &bh4[2 * q]);
#pragma unroll
                for (int mt = 0; mt < 4; mt++)
#pragma unroll
                    for (int q = 0; q < 2; q++)
                        mma_bf16(acc[mt][p * 2 + q], afh[mt], &bl4[2 * q]);
#pragma unroll
                for (int mt = 0; mt < 4; mt++)
#pragma unroll
                    for (int q = 0; q < 2; q++)
                        mma_bf16(acc[mt][p * 2 + q], afl[mt], &bh4[2 * q]);
            }
        }
        __syncthreads();
    }
}

// =============================================================================
// Kernel A: PW = P @ Wt^T
// =============================================================================
__global__ __launch_bounds__(256, 2) void k_pw_mma() {
    extern __shared__ __align__(16) char smraw[];
    __nv_bfloat16* sm = (__nv_bfloat16*)smraw;
    const int bm = blockIdx.y * 128, bn = blockIdx.x * 128;
    const int tid = threadIdx.x, warp = tid >> 5, lane = tid & 31;
    const int wm = (warp >> 2) * 64, wn = (warp & 3) * 32;
    const int gid = lane >> 2, tig = lane & 3;
    const int lrow = tid >> 1, lseg = (tid & 1) * 16;

    float acc[4][4][4];
#pragma unroll
    for (int mt = 0; mt < 4; mt++)
#pragma unroll
        for (int nt = 0; nt < 4; nt++)
#pragma unroll
            for (int e = 0; e < 4; e++) acc[mt][nt][e] = 0.0f;

    gemm_nt_body<DH>(sm, g_Phi, g_Plo, g_Wthi, g_Wtlo,
                     (size_t)(bm + lrow) * DH + lseg,
                     (size_t)(bn + lrow) * DH + lseg,
                     acc, wm, wn, lane);

#pragma unroll
    for (int mt = 0; mt < 4; mt++) {
        int r0 = bm + wm + mt * 16 + gid, r1 = r0 + 8;
#pragma unroll
        for (int nt = 0; nt < 4; nt++) {
            int c = bn + wn + nt * 8 + tig * 2;
            float* d = acc[mt][nt];
            BF2 h0, l0, h1, l1;
            split_bf16(d[0], h0.h[0], l0.h[0]);
            split_bf16(d[1], h0.h[1], l0.h[1]);
            split_bf16(d[2], h1.h[0], l1.h[0]);
            split_bf16(d[3], h1.h[1], l1.h[1]);
            *(unsigned*)&g_PWhi[(size_t)r0 * DH + c] = h0.u;
            *(unsigned*)&g_PWlo[(size_t)r0 * DH + c] = l0.u;
            *(unsigned*)&g_PWhi[(size_t)r1 * DH + c] = h1.u;
            *(unsigned*)&g_PWlo[(size_t)r1 * DH + c] = l1.u;
        }
    }
}

// =============================================================================
// Kernel B: sim[b] = PW[b] @ H[b]^T + bias + mask, WITH fused stats partials
// =============================================================================
__global__ __launch_bounds__(256, 2) void k_sim(const int* __restrict__ pmask,
                                                const int* __restrict__ hmask,
                                                const float* __restrict__ bias) {
    extern __shared__ __align__(16) char smraw[];
    __nv_bfloat16* sm = (__nv_bfloat16*)smraw;
    const int b = blockIdx.z;
    const int bm = blockIdx.y * 128, bn = blockIdx.x * 128;
    const int tid = threadIdx.x, warp = tid >> 5, lane = tid & 31;
    const int wm = (warp >> 2) * 64, wn = (warp & 3) * 32;
    const int gid = lane >> 2, tig = lane & 3;
    const int lrow = tid >> 1, lseg = (tid & 1) * 16;

    float acc[4][4][4];
#pragma unroll
    for (int mt = 0; mt < 4; mt++)
#pragma unroll
        for (int nt = 0; nt < 4; nt++)
#pragma unroll
            for (int e = 0; e < 4; e++) acc[mt][nt][e] = 0.0f;

    gemm_nt_body<DH>(sm, g_PWhi, g_PWlo, g_Hhi, g_Hlo,
                     ((size_t)b * LL + bm + lrow) * DH + lseg,
                     ((size_t)b * LL + bn + lrow) * DH + lseg,
                     acc, wm, wn, lane);

    const float bb = bias[0];
#pragma unroll
    for (int mt = 0; mt < 4; mt++) {
        int r0 = bm + wm + mt * 16 + gid, r1 = r0 + 8;
        float pm0 = (float)pmask[b * LL + r0];
        float pm1 = (float)pmask[b * LL + r1];
#pragma unroll
        for (int nt = 0; nt < 4; nt++) {
            int c = bn + wn + nt * 8 + tig * 2;
            float hm0 = (float)hmask[b * LL + c];
            float hm1 = (float)hmask[b * LL + c + 1];
            float* d = acc[mt][nt];
            d[0] += bb + (1.0f - pm0 * hm0) * NEGINF;
            d[1] += bb + (1.0f - pm0 * hm1) * NEGINF;
            d[2] += bb + (1.0f - pm1 * hm0) * NEGINF;
            d[3] += bb + (1.0f - pm1 * hm1) * NEGINF;
            *(float2*)&g_sim[((size_t)b * LL + r0) * LL + c] = make_float2(d[0], d[1]);
            *(float2*)&g_sim[((size_t)b * LL + r1) * LL + c] = make_float2(d[2], d[3]);
        }
    }

    // ---- fused stats partials (reuse smem as float scratch) ----
    float* S = (float*)sm;
    float* rowmS = S;            // [4][128]
    float* rowsS = S + 512;      // [4][128]
    float* colmS = S + 1024;     // [2][128]
    const int wng = warp & 3, wrow = warp >> 2;
    __syncthreads();

#pragma unroll
    for (int mt = 0; mt < 4; mt++) {
        float m0 = FLT_LOW, m1 = FLT_LOW;
#pragma unroll
        for (int nt = 0; nt < 4; nt++) {
            m0 = fmaxf(m0, fmaxf(acc[mt][nt][0], acc[mt][nt][1]));
            m1 = fmaxf(m1, fmaxf(acc[mt][nt][2], acc[mt][nt][3]));
        }
        m0 = fmaxf(m0, __shfl_xor_sync(0xffffffffu, m0, 1));
        m0 = fmaxf(m0, __shfl_xor_sync(0xffffffffu, m0, 2));
        m1 = fmaxf(m1, __shfl_xor_sync(0xffffffffu, m1, 1));
        m1 = fmaxf(m1, __shfl_xor_sync(0xffffffffu, m1, 2));
        if (tig == 0) {
            rowmS[wng * 128 + wm + mt * 16 + gid]     = m0;
            rowmS[wng * 128 + wm + mt * 16 + gid + 8] = m1;
        }
    }
#pragma unroll
    for (int nt = 0; nt < 4; nt++) {
        float c0 = FLT_LOW, c1 = FLT_LOW;
#pragma unroll
        for (int mt = 0; mt < 4; mt++) {
            c0 = fmaxf(c0, fmaxf(acc[mt][nt][0], acc[mt][nt][2]));
            c1 = fmaxf(c1, fmaxf(acc[mt][nt][1], acc[mt][nt][3]));
        }
        c0 = fmaxf(c0, __shfl_xor_sync(0xffffffffu, c0, 4));
        c0 = fmaxf(c0, __shfl_xor_sync(0xffffffffu, c0, 8));
        c0 = fmaxf(c0, __shfl_xor_sync(0xffffffffu, c0, 16));
        c1 = fmaxf(c1, __shfl_xor_sync(0xffffffffu, c1, 4));
        c1 = fmaxf(c1, __shfl_xor_sync(0xffffffffu, c1, 8));
        c1 = fmaxf(c1, __shfl_xor_sync(0xffffffffu, c1, 16));
        if (gid == 0) {
            colmS[wrow * 128 + wn + nt * 8 + tig * 2]     = c0;
            colmS[wrow * 128 + wn + nt * 8 + tig * 2 + 1] = c1;
        }
    }
    __syncthreads();

#pragma unroll
    for (int mt = 0; mt < 4; mt++) {
        int lr0 = wm + mt * 16 + gid, lr1 = lr0 + 8;
        float m0 = fmaxf(fmaxf(rowmS[lr0], rowmS[128 + lr0]),
                         fmaxf(rowmS[256 + lr0], rowmS[384 + lr0]));
        float m1 = fmaxf(fmaxf(rowmS[lr1], rowmS[128 + lr1]),
                         fmaxf(rowmS[256 + lr1], rowmS[384 + lr1]));
        float s0 = 0.0f, s1 = 0.0f;
#pragma unroll
        for (int nt = 0; nt < 4; nt++) {
            s0 += __expf(acc[mt][nt][0] - m0) + __expf(acc[mt][nt][1] - m0);
            s1 += __expf(acc[mt][nt][2] - m1) + __expf(acc[mt][nt][3] - m1);
        }
        s0 += __shfl_xor_sync(0xffffffffu, s0, 1);
        s0 += __shfl_xor_sync(0xffffffffu, s0, 2);
        s1 += __shfl_xor_sync(0xffffffffu, s1, 1);
        s1 += __shfl_xor_sync(0xffffffffu, s1, 2);
        if (tig == 0) {
            rowsS[wng * 128 + lr0] = s0;
            rowsS[wng * 128 + lr1] = s1;
        }
    }
    __syncthreads();

    if (tid < 128) {
        float m = fmaxf(fmaxf(rowmS[tid], rowmS[128 + tid]),
                        fmaxf(rowmS[256 + tid], rowmS[384 + tid]));
        float s = rowsS[tid] + rowsS[128 + tid] + rowsS[256 + tid] + rowsS[384 + tid];
        size_t ro = (size_t)blockIdx.x * (NB * LL) + (size_t)b * LL + bm + tid;
        g_rowpm[ro] = m;
        g_rowps[ro] = s;
        float cm = fmaxf(colmS[tid], colmS[128 + tid]);
        g_colpart[((size_t)b * 8 + blockIdx.y) * LL + bn + tid] = cm;
    }
}

// =============================================================================
// Kernel C2: combine 8 row partials -> rowmax / rowinv
// =============================================================================
__global__ void k_finstats() {
    int row = blockIdx.x * 256 + threadIdx.x;     // < NB*LL
    float mj[8];
    float m = FLT_LOW;
#pragma unroll
    for (int j = 0; j < 8; j++) {
        mj[j] = g_rowpm[j * (NB * LL) + row];
        m = fmaxf(m, mj[j]);
    }
    float s = 0.0f;
#pragma unroll
    for (int j = 0; j < 8; j++)
        s += g_rowps[j * (NB * LL) + row] * __expf(mj[j] - m);
    g_rowmax[row] = m;
    g_rowinv[row] = 1.0f / s;
}

// =============================================================================
// Kernel D: aligned_hyp[b] = softmax(sim[b]) @ H[b]
// fp16 2-product: A = f16(probs) single; B = H f16 hi/lo split.
// =============================================================================
#define AV_AH 0
#define AV_B(s) (5120 + (s) * 8704)
#define AV_SRAW_H 22528
#define AV_SMEM_BYTES (22528 * 2 + 2 * 128 * 36 * 4)

__global__ __launch_bounds__(256, 2) void k_av(float* __restrict__ out) {
    extern __shared__ __align__(16) char smraw[];
    __half* sm = (__half*)smraw;
    float* Sraw = (float*)(sm + AV_SRAW_H);
    const int b = blockIdx.z;
    const int bm = blockIdx.y * 128, bn = blockIdx.x * 128;   // bn over DH
    const int tid = threadIdx.x, warp = tid >> 5, lane = tid & 31;
    const int wm = (warp >> 2) * 64, wn = (warp & 3) * 32;
    const int gid = lane >> 2, tig = lane & 3;
    const int lrow = tid >> 1, lseg = (tid & 1) * 16;
    const int arow = wm + (lane & 15), acol = (lane >> 4) * 8;
    const int tkr = (lane & 7) + ((lane >> 3) & 1) * 8;
    const int tdc = ((lane >> 4) & 1) * 8;
    const int qr = tid >> 3, dc = (tid & 7) * 16;

    const float rm = g_rowmax[b * LL + bm + lrow];
    const float ri = g_rowinv[b * LL + bm + lrow];
    const float* sp = &g_sim[((size_t)b * LL + bm + lrow) * LL + lseg];

    float acc[4][4][4];
#pragma unroll
    for (int mt = 0; mt < 4; mt++)
#pragma unroll
        for (int nt = 0; nt < 4; nt++)
#pragma unroll
            for (int e = 0; e < 4; e++) acc[mt][nt][e] = 0.0f;

    {
        float* sr = Sraw + lrow * 36 + lseg;
        cpa16(sr,      sp);
        cpa16(sr + 4,  sp + 4);
        cpa16(sr + 8,  sp + 8);
        cpa16(sr + 12, sp + 12);
        size_t hb = ((size_t)b * LL + qr) * DH + bn + dc;
        __half* bh = sm + AV_B(0) + qr * 136 + dc;
        cpa16(bh,            &g_Hfh[hb]);
        cpa16(bh + 8,        &g_Hfh[hb + 8]);
        cpa16(bh + 4352,     &g_Hfl[hb]);
        cpa16(bh + 4352 + 8, &g_Hfl[hb + 8]);
        CP_COMMIT;
    }
    int s = 0;
    for (int k0 = 0; k0 < LL; k0 += 32, s ^= 1) {
        if (k0 + 32 < LL) {
            float* sr = Sraw + (s ^ 1) * 128 * 36 + lrow * 36 + lseg;
            const float* spn = sp + k0 + 32;
            cpa16(sr,      spn);
            cpa16(sr + 4,  spn + 4);
            cpa16(sr + 8,  spn + 8);
            cpa16(sr + 12, spn + 12);
            size_t hb = ((size_t)b * LL + k0 + 32 + qr) * DH + bn + dc;
            __half* bh = sm + AV_B(s ^ 1) + qr * 136 + dc;
            cpa16(bh,            &g_Hfh[hb]);
            cpa16(bh + 8,        &g_Hfh[hb + 8]);
            cpa16(bh + 4352,     &g_Hfl[hb]);
            cpa16(bh + 4352 + 8, &g_Hfl[hb + 8]);
            CP_COMMIT;
            CP_WAIT1;
        } else {
            CP_WAIT0;
        }
        __syncthreads();
        {
            const float* sr = Sraw + s * 128 * 36 + lrow * 36 + lseg;
            HF8 ph0, ph1;
#pragma unroll
            for (int i = 0; i < 8; i++) {
                ph0.h[i] = __float2half_rn(__expf(sr[i] - rm) * ri);
                ph1.h[i] = __float2half_rn(__expf(sr[8 + i] - rm) * ri);
            }
            *(uint4*)(sm + AV_AH + lrow * 40 + lseg)     = ph0.v;
            *(uint4*)(sm + AV_AH + lrow * 40 + lseg + 8) = ph1.v;
        }
        __syncthreads();
        const __half* Bhs = sm + AV_B(s);
        const __half* Bls = Bhs + 4352;
#pragma unroll
        for (int ks = 0; ks < 32; ks += 16) {
            unsigned afh[4][4];
#pragma unroll
            for (int mt = 0; mt < 4; mt++)
                ldsm4(afh[mt], sm32(sm + AV_AH + (arow + mt * 16) * 40 + ks + acol));
#pragma unroll
            for (int p = 0; p < 2; p++) {
                unsigned bh4[4], bl4[4];
                ldsm4t(bh4, sm32(Bhs + (ks + tkr) * 136 + wn + p * 16 + tdc));
                ldsm4t(bl4, sm32(Bls + (ks + tkr) * 136 + wn + p * 16 + tdc));
#pragma unroll
                for (int mt = 0; mt < 4; mt++)
#pragma unroll
                    for (int q = 0; q < 2; q++)
                        mma_f16(acc[mt][p * 2 + q], afh[mt], &bh4[2 * q]);
#pragma unroll
                for (int mt = 0; mt < 4; mt++)
#pragma unroll
                    for (int q = 0; q < 2; q++)
                        mma_f16(acc[mt][p * 2 + q], afh[mt], &bl4[2 * q]);
            }
        }
        __syncthreads();    // guards next prefetch overwriting Bhs(s)/Sraw(s)
    }
#pragma unroll
    for (int mt = 0; mt < 4; mt++) {
        int r0 = bm + wm + mt * 16 + gid, r1 = r0 + 8;
#pragma unroll
        for (int nt = 0; nt < 4; nt++) {
            int c = bn + wn + nt * 8 + tig * 2;
            float* d = acc[mt][nt];
            *(float2*)&out[((size_t)b * LL + r0) * DH + c] = make_float2(d[0], d[1]);
            *(float2*)&out[((size_t)b * LL + r1) * DH + c] = make_float2(d[2], d[3]);
        }
    }
}

// =============================================================================
// Kernel E: per batch — softmax(colmax over 8 partials) @ P -> g_pvec
// =============================================================================
__global__ __launch_bounds__(256) void k_premise(const float* __restrict__ P) {
    const int b = blockIdx.x;
    const int t = threadIdx.x;
    __shared__ float prob[LL];
    __shared__ float red[8];
    float loc[4];
#pragma unroll
    for (int c = 0; c < 4; c++) {
        int q = c * 256 + t;
        float m = FLT_LOW;
#pragma unroll
        for (int j = 0; j < 8; j++)
            m = fmaxf(m, g_colpart[((size_t)b * 8 + j) * LL + q]);
        loc[c] = m;
    }
    float mx = fmaxf(fmaxf(loc[0], loc[1]), fmaxf(loc[2], loc[3]));
#pragma unroll
    for (int o = 16; o > 0; o >>= 1) mx = fmaxf(mx, __shfl_xor_sync(0xffffffffu, mx, o));
    const int w = t >> 5, lane = t & 31;
    if (lane == 0) red[w] = mx;
    __syncthreads();
    mx = red[0];
#pragma unroll
    for (int j = 1; j < 8; j++) mx = fmaxf(mx, red[j]);

    float se = 0.0f;
#pragma unroll
    for (int c = 0; c < 4; c++) {
        float e = __expf(loc[c] - mx);
        prob[c * 256 + t] = e;
        se += e;
    }
#pragma unroll
    for (int o = 16; o > 0; o >>= 1) se += __shfl_xor_sync(0xffffffffu, se, o);
    __syncthreads();
    if (lane == 0) red[w] = se;
    __syncthreads();
    float tot = 0.0f;
#pragma unroll
    for (int j = 0; j < 8; j++) tot += red[j];
    const float inv = 1.0f / tot;

    const float* Pb = P + (size_t)b * LL * DH + t;
    float acc = 0.0f;
#pragma unroll 8
    for (int q = 0; q < LL; q++)
        acc = fmaf(prob[q], Pb[(size_t)q * DH], acc);
    g_pvec[b * DH + t] = acc * inv;
}

// =============================================================================
// Kernel F: broadcast g_pvec -> out[0 : NB*LL*DH)
// =============================================================================
__global__ void k_bcast(float* __restrict__ out) {
    int idx = (blockIdx.x * 256 + threadIdx.x) * 4;
    int b = idx >> 18;
    int d = idx & (DH - 1);
    float4 v = *(const float4*)&g_pvec[b * DH + d];
    *(float4*)&out[idx] = v;
}

// =============================================================================
extern "C" void kernel_launch(void* const* d_in, const int* in_sizes, int n_in,
                              void* d_out, int out_size) {
    const float* P    = (const float*)d_in[0];
    const float* Hh   = (const float*)d_in[1];
    const int*   pm   = (const int*)d_in[2];
    const int*   hm   = (const int*)d_in[3];
    const float* W    = (const float*)d_in[4];
    const float* bias = (const float*)d_in[5];
    float* out = (float*)d_out;

    const int gemm_smem = 2 * STG * 2;            // 81920 bytes
    cudaFuncSetAttribute(k_pw_mma, cudaFuncAttributeMaxDynamicSharedMemorySize, gemm_smem);
    cudaFuncSetAttribute(k_sim,    cudaFuncAttributeMaxDynamicSharedMemorySize, gemm_smem);
    cudaFuncSetAttribute(k_av,     cudaFuncAttributeMaxDynamicSharedMemorySize, AV_SMEM_BYTES);

    k_cvt_all  <<<2 * NHBLK + DH * DH / 256, 256>>>(Hh, P, W);
    k_pw_mma   <<<dim3(DH / 128, (NB * LL) / 128), 256, gemm_smem>>>();
    k_sim      <<<dim3(LL / 128, LL / 128, NB), 256, gemm_smem>>>(pm, hm, bias);
    k_finstats <<<(NB * LL) / 256, 256>>>();
    k_av       <<<dim3(DH / 128, LL / 128, NB), 256, AV_SMEM_BYTES>>>(out + (size_t)NB * LL * DH);
    k_premise  <<<NB, 256>>>(P);
    k_bcast    <<<(NB * LL * DH) / (256 * 4), 256>>>(out);
}